// round 17
// baseline (speedup 1.0000x reference)
#include <cuda_runtime.h>
#include <cuda_bf16.h>
#include <cuda_fp16.h>
#include <cstdint>

#define B_ROWS 8192
#define DFEAT  512
#define KOUT   1024

// Scratch (__device__ globals; no dynamic allocation allowed)
__device__ __align__(16) unsigned char g_xf8[B_ROWS * DFEAT];   // 4 MB e4m3
__device__ __align__(16) unsigned char g_wf8[KOUT * DFEAT];     // 0.5 MB e4m3
__device__ float g_xsq[B_ROWS];
__device__ float g_wsq[KOUT];
__device__ float g_rowsum[B_ROWS];
__device__ int   g_cnt[64];

// ---------------------------------------------------------------------------
// Kernel 1: convert x,w to e4m3 + fp32 row squared norms. 4 rows per warp.
// Also zeroes g_rowsum / g_cnt for the fused-norm reduction (graph-safe).
// ---------------------------------------------------------------------------
__device__ __forceinline__ uint16_t pack_e4m3x2(float hi, float lo) {
    uint16_t h;
    asm("cvt.rn.satfinite.e4m3x2.f32 %0, %1, %2;" : "=h"(h) : "f"(hi), "f"(lo));
    return h;
}

__global__ void prep_kernel(const float* __restrict__ x, const float* __restrict__ w) {
    int gt = blockIdx.x * blockDim.x + threadIdx.x;
    if (gt < B_ROWS) g_rowsum[gt] = 0.0f;
    if (gt < 64)     g_cnt[gt] = 0;

    int gw   = gt >> 5;
    int lane = threadIdx.x & 31;
    int r0 = gw * 4;

    const float* src[4];
    unsigned char* dst[4];
    float* sqp[4];
    int sqi[4];
#pragma unroll
    for (int j = 0; j < 4; j++) {
        int r = r0 + j;
        if (r < B_ROWS) {
            src[j] = x + (size_t)r * DFEAT;
            dst[j] = g_xf8 + (size_t)r * DFEAT;
            sqp[j] = g_xsq; sqi[j] = r;
        } else {
            int rr = r - B_ROWS;
            src[j] = w + (size_t)rr * DFEAT;
            dst[j] = g_wf8 + (size_t)rr * DFEAT;
            sqp[j] = g_wsq; sqi[j] = rr;
        }
    }

    float4 v[4][4];
#pragma unroll
    for (int j = 0; j < 4; j++)
#pragma unroll
        for (int i = 0; i < 4; i++)
            v[j][i] = *reinterpret_cast<const float4*>(src[j] + i * 128 + lane * 4);

#pragma unroll
    for (int j = 0; j < 4; j++) {
        float s = 0.0f;
#pragma unroll
        for (int i = 0; i < 4; i++) {
            float4 q = v[j][i];
            s += q.x * q.x + q.y * q.y + q.z * q.z + q.w * q.w;
            uint32_t pk = ((uint32_t)pack_e4m3x2(q.w, q.z) << 16)
                        |  (uint32_t)pack_e4m3x2(q.y, q.x);
            *reinterpret_cast<uint32_t*>(dst[j] + i * 128 + lane * 4) = pk;
        }
#pragma unroll
        for (int off = 16; off >= 1; off >>= 1)
            s += __shfl_xor_sync(0xFFFFFFFFu, s, off);
        if (lane == 0) sqp[j][sqi[j]] = s;
    }
}

// ---------------------------------------------------------------------------
// Kernel 2: e4m3 mma.sync (m16n8k32, f16 acc) GEMM + fused normalization.
// Grid 512 (one 128x128 tile per CTA), 3 CTAs/SM (24 warps -> latency hiding),
// NSTAGE=2 cp.async pipeline. Cross-CTA row-sum reduction over groups of 8
// consecutive blockIdx (launch-order safe across the wave boundary).
// ---------------------------------------------------------------------------
#define TILE_BYTES (128 * 144)
#define STAGE_BYTES (2 * TILE_BYTES)      // 36864
#define NSTAGE 2
#define OFF_SQ  (NSTAGE * STAGE_BYTES)    // 73728
#define OFF_SUM (OFF_SQ + 1024)           // 74752
#define GEMM_SMEM (OFF_SUM + 1024)        // 75776 -> 3 CTAs/SM (227328 <= 228K)

__device__ __forceinline__ void ldmatrix_x4(uint32_t& r0, uint32_t& r1,
                                            uint32_t& r2, uint32_t& r3,
                                            uint32_t saddr) {
    asm volatile("ldmatrix.sync.aligned.m8n8.x4.shared.b16 {%0,%1,%2,%3}, [%4];"
                 : "=r"(r0), "=r"(r1), "=r"(r2), "=r"(r3) : "r"(saddr));
}

// fp8 mma with f16 accumulator
__device__ __forceinline__ void mma_fp8_h(uint32_t* d, const uint32_t* a,
                                          uint32_t b0, uint32_t b1) {
    asm volatile(
        "mma.sync.aligned.m16n8k32.row.col.f16.e4m3.e4m3.f16 "
        "{%0,%1}, {%2,%3,%4,%5}, {%6,%7}, {%0,%1};"
        : "+r"(d[0]), "+r"(d[1])
        : "r"(a[0]), "r"(a[1]), "r"(a[2]), "r"(a[3]), "r"(b0), "r"(b1));
}

__device__ __forceinline__ void cp16(uint32_t s, const void* g) {
    asm volatile("cp.async.cg.shared.global [%0], [%1], 16;" :: "r"(s), "l"(g));
}

__device__ __forceinline__ void load_stage(uint32_t sbase, int stage, int kc,
                                           int m0, int n0, int tid) {
    const char* gA = (const char*)g_xf8 + (size_t)m0 * 512 + (size_t)kc * 128;
    const char* gB = (const char*)g_wf8 + (size_t)n0 * 512 + (size_t)kc * 128;
    uint32_t aB = sbase + stage * STAGE_BYTES;
    uint32_t bB = aB + TILE_BYTES;
#pragma unroll
    for (int i = 0; i < 4; i++) {
        int idx = tid + i * 256;
        int row = idx >> 3;
        int cb  = (idx & 7) << 4;
        cp16(aB + row * 144 + cb, gA + (size_t)row * 512 + cb);
        cp16(bB + row * 144 + cb, gB + (size_t)row * 512 + cb);
    }
}

__global__ __launch_bounds__(256, 3) void gemm_kernel(float* __restrict__ out) {
    extern __shared__ __align__(16) char smem[];
    uint32_t sbase;
    asm("{ .reg .u64 t; cvta.to.shared.u64 t, %1; cvt.u32.u64 %0, t; }"
        : "=r"(sbase) : "l"(smem));

    const int tid  = threadIdx.x;
    const int lane = tid & 31;
    const int warp = tid >> 5;
    const int wm = warp & 3;
    const int wn = warp >> 2;

    float* sXsq = reinterpret_cast<float*>(smem + OFF_SQ);
    float* sWsq = sXsq + 128;
    float* ssum = reinterpret_cast<float*>(smem + OFF_SUM);

    const int a_row = (lane & 15);
    const int a_cb  = (lane >> 4) << 4;
    const int b_r   = lane & 7;
    const int b_sel = lane >> 3;
    const int b_nof = ((b_sel >> 1) << 3) + b_r;
    const int b_kb  = (b_sel & 1) << 4;
    const int qt = lane >> 2;
    const int qr = lane & 3;

    const int ygrp = (int)blockIdx.x >> 3;
    const int m0 = ygrp * 128;
    const int n0 = ((int)blockIdx.x & 7) * 128;

    if (tid < 128) {
        sXsq[tid] = g_xsq[m0 + tid];
        sWsq[tid] = g_wsq[n0 + tid];
    }

    uint32_t acc[2][8][2];   // f16x2 accumulators
#pragma unroll
    for (int mi = 0; mi < 2; mi++)
#pragma unroll
        for (int ni = 0; ni < 8; ni++) {
            acc[mi][ni][0] = 0u;
            acc[mi][ni][1] = 0u;
        }

    load_stage(sbase, 0, 0, m0, n0, tid);
    asm volatile("cp.async.commit_group;" ::: "memory");
    load_stage(sbase, 1, 1, m0, n0, tid);
    asm volatile("cp.async.commit_group;" ::: "memory");

#pragma unroll 1
    for (int kc = 0; kc < 4; kc++) {
        if (kc < 3) asm volatile("cp.async.wait_group 1;" ::: "memory");
        else        asm volatile("cp.async.wait_group 0;" ::: "memory");
        __syncthreads();

        uint32_t aBase = sbase + (kc & 1) * STAGE_BYTES;
        uint32_t bBase = aBase + TILE_BYTES;

#pragma unroll
        for (int ks = 0; ks < 128; ks += 32) {
            uint32_t af[2][4];
#pragma unroll
            for (int mi = 0; mi < 2; mi++) {
                int r = wm * 32 + mi * 16 + a_row;
                ldmatrix_x4(af[mi][0], af[mi][1], af[mi][2], af[mi][3],
                            aBase + r * 144 + ks + a_cb);
            }
            uint32_t bfr[4][4];
#pragma unroll
            for (int j = 0; j < 4; j++) {
                int n = wn * 64 + j * 16 + b_nof;
                ldmatrix_x4(bfr[j][0], bfr[j][1], bfr[j][2], bfr[j][3],
                            bBase + n * 144 + ks + b_kb);
            }
#pragma unroll
            for (int mi = 0; mi < 2; mi++)
#pragma unroll
                for (int ni = 0; ni < 8; ni++) {
                    int j = ni >> 1, h = (ni & 1) * 2;
                    mma_fp8_h(acc[mi][ni], af[mi], bfr[j][h], bfr[j][h + 1]);
                }
        }
        if (kc + 2 < 4) {
            __syncthreads();   // all warps done reading stage kc&1
            load_stage(sbase, kc & 1, kc + 2, m0, n0, tid);
            asm volatile("cp.async.commit_group;" ::: "memory");
        }
    }

    // ---- pass 1: row sums from accumulators (q computed on the fly) ----
    float s[2][2] = {{0.0f, 0.0f}, {0.0f, 0.0f}};
#pragma unroll
    for (int mi = 0; mi < 2; mi++) {
        int lr = wm * 32 + mi * 16 + qt;
        float xs0 = sXsq[lr];
        float xs1 = sXsq[lr + 8];
#pragma unroll
        for (int ni = 0; ni < 8; ni++) {
            int nl = wn * 64 + ni * 8 + qr * 2;
            float w0 = sWsq[nl];
            float w1 = sWsq[nl + 1];
            float2 f0 = __half22float2(*reinterpret_cast<__half2*>(&acc[mi][ni][0]));
            float2 f1 = __half22float2(*reinterpret_cast<__half2*>(&acc[mi][ni][1]));
            s[mi][0] += 1.0f / (1.0f + fmaxf(xs0 + w0 - 2.0f * f0.x, 0.0f))
                      + 1.0f / (1.0f + fmaxf(xs0 + w1 - 2.0f * f0.y, 0.0f));
            s[mi][1] += 1.0f / (1.0f + fmaxf(xs1 + w0 - 2.0f * f1.x, 0.0f))
                      + 1.0f / (1.0f + fmaxf(xs1 + w1 - 2.0f * f1.y, 0.0f));
        }
    }
#pragma unroll
    for (int mi = 0; mi < 2; mi++)
#pragma unroll
        for (int h = 0; h < 2; h++) {
            s[mi][h] += __shfl_xor_sync(0xFFFFFFFFu, s[mi][h], 1);
            s[mi][h] += __shfl_xor_sync(0xFFFFFFFFu, s[mi][h], 2);
        }
    if (qr == 0) {
#pragma unroll
        for (int mi = 0; mi < 2; mi++)
#pragma unroll
            for (int h = 0; h < 2; h++)
                ssum[(wm * 32 + mi * 16 + h * 8 + qt) * 2 + wn] = s[mi][h];
    }
    __syncthreads();
    if (tid < 128)
        atomicAdd(&g_rowsum[m0 + tid], ssum[2 * tid] + ssum[2 * tid + 1]);
    __threadfence();
    __syncthreads();
    if (tid == 0) {
        atomicAdd(&g_cnt[ygrp], 1);
        while (atomicAdd(&g_cnt[ygrp], 0) < 8) { }
    }
    __syncthreads();

    // ---- pass 2: recompute q from preserved accumulators, scale, write ----
#pragma unroll
    for (int mi = 0; mi < 2; mi++) {
        int lr = wm * 32 + mi * 16 + qt;
        float xs0 = sXsq[lr];
        float xs1 = sXsq[lr + 8];
        float inv0 = 1.0f / __ldcg(&g_rowsum[m0 + lr]);
        float inv1 = 1.0f / __ldcg(&g_rowsum[m0 + lr + 8]);
        int gr0 = (m0 + lr) * KOUT;
        int gr1 = gr0 + 8 * KOUT;
#pragma unroll
        for (int ni = 0; ni < 8; ni++) {
            int nl = wn * 64 + ni * 8 + qr * 2;
            float w0 = sWsq[nl];
            float w1 = sWsq[nl + 1];
            float2 f0 = __half22float2(*reinterpret_cast<__half2*>(&acc[mi][ni][0]));
            float2 f1 = __half22float2(*reinterpret_cast<__half2*>(&acc[mi][ni][1]));
            float q00 = 1.0f / (1.0f + fmaxf(xs0 + w0 - 2.0f * f0.x, 0.0f));
            float q01 = 1.0f / (1.0f + fmaxf(xs0 + w1 - 2.0f * f0.y, 0.0f));
            float q10 = 1.0f / (1.0f + fmaxf(xs1 + w0 - 2.0f * f1.x, 0.0f));
            float q11 = 1.0f / (1.0f + fmaxf(xs1 + w1 - 2.0f * f1.y, 0.0f));
            *reinterpret_cast<float2*>(&out[gr0 + n0 + nl]) =
                make_float2(q00 * inv0, q01 * inv0);
            *reinterpret_cast<float2*>(&out[gr1 + n0 + nl]) =
                make_float2(q10 * inv1, q11 * inv1);
        }
    }
}

// ---------------------------------------------------------------------------
extern "C" void kernel_launch(void* const* d_in, const int* in_sizes, int n_in,
                              void* d_out, int out_size) {
    const float* x = (const float*)d_in[0];   // [8192, 512] f32
    const float* w = (const float*)d_in[1];   // [1024, 512] f32
    float* out = (float*)d_out;               // [8192, 1024] f32

    cudaFuncSetAttribute(gemm_kernel, cudaFuncAttributeMaxDynamicSharedMemorySize,
                         GEMM_SMEM);

    prep_kernel<<<288, 256>>>(x, w);
    gemm_kernel<<<512, 256, GEMM_SMEM>>>(out);
}